// round 10
// baseline (speedup 1.0000x reference)
#include <cuda_runtime.h>
#include <cstdint>

#define BB   64
#define TT   512
#define DH   1024
#define NPROD 24                 // producer CTAs (minimum that stays ahead)

// ---------------- device scratch (static, allocation-free) ----------------
__device__ float g_Gin_ih[1024 * 16];    // [j][d]
__device__ float g_Gin_hh[1024 * 16];    // [j][d]
__device__ float g_G56t_ih[256 * 16];    // [mp][e]  (transposed)
__device__ float g_G56t_hh[256 * 16];    // [mp][e]
__device__ float g_bias4[4096];          // [j][gate]
__device__ float g_ihg[(size_t)BB * TT * 4096]; // t-major: [t][b][j][gate]
__device__ int   g_cnt[TT];              // per-slice completion counters

typedef unsigned long long u64;

// ---------------- packed f32x2 helpers ------------------------------------
__device__ __forceinline__ u64 pk2(float lo, float hi) {
    u64 r; asm("mov.b64 %0, {%1,%2};" : "=l"(r) : "f"(lo), "f"(hi)); return r;
}
__device__ __forceinline__ void upk2(u64 v, float& lo, float& hi) {
    asm("mov.b64 {%0,%1}, %2;" : "=f"(lo), "=f"(hi) : "l"(v));
}
__device__ __forceinline__ u64 ffma2(u64 a, u64 b, u64 c) {
    u64 d; asm("fma.rn.f32x2 %0, %1, %2, %3;" : "=l"(d) : "l"(a), "l"(b), "l"(c));
    return d;
}
__device__ __forceinline__ u64 fadd2(u64 a, u64 b) {
    u64 d; asm("add.rn.f32x2 %0, %1, %2;" : "=l"(d) : "l"(a), "l"(b));
    return d;
}

// ---------------- activations ---------------------------------------------
__device__ __forceinline__ float htanh(float x) {
    float y; asm("tanh.approx.f32 %0, %1;" : "=f"(y) : "f"(x)); return y;
}
__device__ __forceinline__ float hsig(float x) {
    return fmaf(0.5f, htanh(0.5f * x), 0.5f);
}

// ---------------- sync helpers ---------------------------------------------
__device__ __forceinline__ int ldacq(const int* p) {
    int v;
    asm volatile("ld.acquire.gpu.global.b32 %0, [%1];" : "=r"(v) : "l"(p) : "memory");
    return v;
}

// ---------------- kernel 0: build contraction tables (2 CTAs, 1/path) -----
__global__ void k_build(const float* g1i, const float* g2i, const float* g3i,
                        const float* g5i, const float* g6i,
                        const float* g1h, const float* g2h, const float* g3h,
                        const float* g5h, const float* g6h,
                        const float* bih, const float* bhh)
{
    __shared__ float G12[1024]; // [i][j][c]
    int tid  = threadIdx.x;     // 1024 threads
    int path = blockIdx.x;      // 0 = ih, 1 = hh

    const float* g1 = path ? g1h : g1i;
    const float* g2 = path ? g2h : g2i;
    const float* g3 = path ? g3h : g3i;
    const float* g5 = path ? g5h : g5i;
    const float* g6 = path ? g6h : g6i;
    float* Gin  = path ? g_Gin_hh  : g_Gin_ih;
    float* G56t = path ? g_G56t_hh : g_G56t_ih;

    if (path == 0 && tid < TT) g_cnt[tid] = 0;   // reset slice counters

    { // G12[i][j][c] = sum_a g1[i,a] g2[a,j,c]
        int i = tid >> 7, j = (tid >> 4) & 7, c = tid & 15;
        float s = 0.f;
        #pragma unroll
        for (int a = 0; a < 16; a++)
            s = fmaf(g1[i * 16 + a], g2[a * 128 + j * 16 + c], s);
        G12[tid] = s;
    }
    __syncthreads();
    for (int o = tid; o < 16384; o += 1024) {
        int row = o >> 4, d = o & 15;
        int i = row >> 7, j = (row >> 4) & 7, k = row & 15;
        float s = 0.f;
        #pragma unroll
        for (int c = 0; c < 16; c++)
            s = fmaf(G12[i * 128 + j * 16 + c], g3[c * 256 + k * 16 + d], s);
        Gin[row * 16 + d] = s;
    }
    for (int o = tid; o < 4096; o += 1024) {
        int e = o >> 8, m = (o >> 4) & 15, p = o & 15;
        float s = 0.f;
        #pragma unroll
        for (int f = 0; f < 16; f++)
            s = fmaf(g5[e * 256 + m * 16 + f], g6[f * 16 + p], s);
        G56t[(m * 16 + p) * 16 + e] = s;
    }
    if (path == 0) { // bias reindexed to [j][gate]
        int j = tid;
        float4 v;
        v.x = bih[j]        + bhh[j];
        v.y = bih[1024 + j] + bhh[1024 + j];
        v.z = bih[2048 + j] + bhh[2048 + j];
        v.w = bih[3072 + j] + bhh[3072 + j];
        ((float4*)g_bias4)[j] = v;
    }
}

// ---------------- fused kernel: producer (24 CTAs) + recurrence (64 CTAs) --
__global__ void __launch_bounds__(512, 1)
k_fused(const float* __restrict__ x, const float* __restrict__ g4i,
        const float* __restrict__ g4h, float* __restrict__ out)
{
    // ---- shared memory (union of both roles; <48KB static) ----
    __shared__ __align__(16) float hdup[2048];   // rec: h duplicated {h,h}
    __shared__ u64 g4p[8][256];                  // rec: paired g4
    __shared__ __align__(16) float Ash[256];     // rec: A
    __shared__ u64 ppu[16][8];                   // rec: warp partials
    __shared__ __align__(16) float xs[2][1024];  // prod: x rows
    __shared__ float pp[2][16][17];              // prod
    __shared__ float ihpS[2][16];                // prod
    __shared__ __align__(16) float A2[2][256];   // prod

    int tid = threadIdx.x;
    const unsigned FULL = 0xffffffffu;

    if (blockIdx.x >= BB) {
        // ================= PRODUCER =================
        int p    = blockIdx.x - BB;          // 0..NPROD-1
        int half = tid >> 8;                 // 0/1: two rows per iter
        int ht   = tid & 255;

        // loop-invariant tables
        u64 Gp[8];
        {
            const u64* gt = (const u64*)(g_G56t_ih + ht * 16);
            #pragma unroll
            for (int i = 0; i < 8; i++) Gp[i] = gt[i];
        }
        float4 bv[4];
        #pragma unroll
        for (int k = 0; k < 4; k++) bv[k] = ((const float4*)g_bias4)[k * 256 + ht];

        for (int r0 = 2 * p; r0 < BB * TT; r0 += 2 * NPROD) {
            int row = r0 + half;             // t-major row index
            bool act = row < BB * TT;
            int bb = row & 63, t = row >> 6;

            if (act) {
                const float* xrow = x + ((size_t)bb * TT + t) * 1024;
                ((float4*)xs[half])[ht] = ((const float4*)xrow)[ht];
            }
            __syncthreads();
            if (act) { // partial: ihp[d] over 64-j chunk
                int d = ht & 15, ch = ht >> 4;
                const float* gp = g_Gin_ih + (ch * 64) * 16 + d;
                const float* xp = xs[half] + ch * 64;
                float s = 0.f;
                #pragma unroll
                for (int u = 0; u < 64; u++) s = fmaf(xp[u], gp[u * 16], s);
                pp[half][ch][d] = s;
            }
            __syncthreads();
            if (act && ht < 16) {
                float s = 0.f;
                #pragma unroll
                for (int c2 = 0; c2 < 16; c2++) s += pp[half][c2][ht];
                ihpS[half][ht] = s;
            }
            __syncthreads();
            if (act) { // A[n][e]
                float s = 0.f;
                #pragma unroll
                for (int d = 0; d < 16; d++)
                    s = fmaf(ihpS[half][d], __ldg(g4i + d * 256 + ht), s);
                A2[half][ht] = s;
            }
            __syncthreads();
            if (act) { // stage2 -> g_ihg (t-major)
                float* outp = g_ihg + (size_t)row * 4096;
                #pragma unroll
                for (int k = 0; k < 4; k++) {
                    u64 a0 = 0ull, a1 = 0ull, a2 = 0ull, a3 = 0ull;
                    const ulonglong2* Ar0 = (const ulonglong2*)(A2[half] + (0 * 4 + k) * 16);
                    const ulonglong2* Ar1 = (const ulonglong2*)(A2[half] + (1 * 4 + k) * 16);
                    const ulonglong2* Ar2 = (const ulonglong2*)(A2[half] + (2 * 4 + k) * 16);
                    const ulonglong2* Ar3 = (const ulonglong2*)(A2[half] + (3 * 4 + k) * 16);
                    #pragma unroll
                    for (int i = 0; i < 4; i++) {
                        ulonglong2 w0 = Ar0[i], w1 = Ar1[i], w2 = Ar2[i], w3 = Ar3[i];
                        a0 = ffma2(w0.x, Gp[2*i], a0); a0 = ffma2(w0.y, Gp[2*i+1], a0);
                        a1 = ffma2(w1.x, Gp[2*i], a1); a1 = ffma2(w1.y, Gp[2*i+1], a1);
                        a2 = ffma2(w2.x, Gp[2*i], a2); a2 = ffma2(w2.y, Gp[2*i+1], a2);
                        a3 = ffma2(w3.x, Gp[2*i], a3); a3 = ffma2(w3.y, Gp[2*i+1], a3);
                    }
                    float l0, h0, l1, h1, l2, h2, l3, h3;
                    upk2(a0, l0, h0); upk2(a1, l1, h1);
                    upk2(a2, l2, h2); upk2(a3, l3, h3);
                    float4 v;
                    v.x = l0 + h0 + bv[k].x; v.y = l1 + h1 + bv[k].y;
                    v.z = l2 + h2 + bv[k].z; v.w = l3 + h3 + bv[k].w;
                    ((float4*)outp)[k * 256 + ht] = v;
                }
            }
            __syncthreads();
            __threadfence();                 // rows visible before count
            if (ht == 0 && act) atomicAdd(&g_cnt[t], 1);
        }
        return;
    }

    // ================= RECURRENCE (CTAs 0..63) =================
    int b = blockIdx.x;

    for (int i = tid; i < 2048; i += 512) {
        int qq = i >> 8, col = i & 255;
        g4p[qq][col] = pk2(g4h[(2 * qq) * 256 + col], g4h[(2 * qq + 1) * 256 + col]);
        hdup[i] = 0.f;
        hdup[i + 2048 - 2048] = 0.f;
    }
    // zero remaining hdup (2048 total, loop above covers 2048? i<2048 step512 x4 -> 4 elems/thread) — redo cleanly:
    hdup[tid] = 0.f;
    hdup[tid + 512] = 0.f;
    hdup[tid + 1024] = 0.f;
    hdup[tid + 1536] = 0.f;

    // phase-1 constants
    int q  = tid & 7;
    int ch = tid >> 3;
    u64 Grp1[8], Grp2[8];
    {
        const float* gb1 = g_Gin_hh + (size_t)(ch * 8) * 16 + 2 * q;
        const float* gb2 = gb1 + 512 * 16;
        #pragma unroll
        for (int u = 0; u < 8; u++) {
            Grp1[u] = *(const u64*)(gb1 + u * 16);
            Grp2[u] = *(const u64*)(gb2 + u * 16);
        }
    }
    // stage-2 constants: adjacent unit pair
    int j0  = 2 * tid;
    int mp1 = j0 & 255, mp2 = mp1 + 1;
    int nr  = tid >> 7;
    u64 Gp1[8], Gp2[8];
    {
        const u64* gt1 = (const u64*)(g_G56t_hh + mp1 * 16);
        const u64* gt2 = (const u64*)(g_G56t_hh + mp2 * 16);
        #pragma unroll
        for (int i = 0; i < 8; i++) { Gp1[i] = gt1[i]; Gp2[i] = gt2[i]; }
    }
    int warp = tid >> 5, lane = tid & 31;

    float h1 = 0.f, c1 = 0.f, h2 = 0.f, c2 = 0.f;
    const float* ihp = g_ihg + (size_t)b * 4096 + (size_t)j0 * 4; // t-major
    float* outb = out + (size_t)b * TT * DH;

    __syncthreads();

    // wait for slice 0, then load step-0 gates; spec-load slice-1 counter
    while (ldacq(&g_cnt[0]) < BB) { }
    float4 ihg1 = ((const float4*)ihp)[0];
    float4 ihg2 = ((const float4*)ihp)[1];
    int cN = ldacq(&g_cnt[1]);

    for (int t = 0; t < TT; t++) {
        // ---- ensure slice t+1 ready (prefetch target), usually free ----
        int sl = (t + 1 < TT) ? (t + 1) : (TT - 1);
        if (cN < BB) { do { cN = ldacq(&g_cnt[sl]); } while (cN < BB); }

        // ---- prefetch next step's ih gates (t-major stride) ----
        int tn = (t + 1 < TT) ? (t + 1) : t;
        const float4* np = (const float4*)(ihp + (size_t)tn * (BB * 4096));
        float4 ihg1n = np[0];
        float4 ihg2n = np[1];

        // ---- phase 1: partial P, pre-duplicated h pairs (no pk2 movs) ----
        const ulonglong2* hp1 = (const ulonglong2*)(hdup + ch * 16);
        const ulonglong2* hp2 = (const ulonglong2*)(hdup + 1024 + ch * 16);
        u64 pa, pb;
        {
            ulonglong2 wA = hp1[0], wB = hp2[0];
            pa = ffma2(wA.x, Grp1[0], 0ull); pa = ffma2(wA.y, Grp1[1], pa);
            pb = ffma2(wB.x, Grp2[0], 0ull); pb = ffma2(wB.y, Grp2[1], pb);
            wA = hp1[1]; wB = hp2[1];
            pa = ffma2(wA.x, Grp1[2], pa);   pa = ffma2(wA.y, Grp1[3], pa);
            pb = ffma2(wB.x, Grp2[2], pb);   pb = ffma2(wB.y, Grp2[3], pb);
            wA = hp1[2]; wB = hp2[2];
            pa = ffma2(wA.x, Grp1[4], pa);   pa = ffma2(wA.y, Grp1[5], pa);
            pb = ffma2(wB.x, Grp2[4], pb);   pb = ffma2(wB.y, Grp2[5], pb);
            wA = hp1[3]; wB = hp2[3];
            pa = ffma2(wA.x, Grp1[6], pa);   pa = ffma2(wA.y, Grp1[7], pa);
            pb = ffma2(wB.x, Grp2[6], pb);   pb = ffma2(wB.y, Grp2[7], pb);
        }
        u64 part = fadd2(pa, pb);
        part = fadd2(part, __shfl_xor_sync(FULL, part, 8));
        part = fadd2(part, __shfl_xor_sync(FULL, part, 16));
        if (lane < 8) ppu[warp][lane] = part;

        // spec-load next slice counter (checked next step; latency hidden)
        int sl2 = (t + 2 < TT) ? (t + 2) : (TT - 1);
        int cN2 = ldacq(&g_cnt[sl2]);
        __syncthreads();                               // BAR1

        // ---- fused reduce + stage 1 (warps 0-7; col = tid) ----
        if (tid < 256) {
            int w0 = lane >> 3, qq = lane & 7;
            u64 s = fadd2(fadd2(ppu[w0][qq], ppu[w0 + 4][qq]),
                          fadd2(ppu[w0 + 8][qq], ppu[w0 + 12][qq]));
            s = fadd2(s, __shfl_xor_sync(FULL, s, 8));
            s = fadd2(s, __shfl_xor_sync(FULL, s, 16));
            u64 acc = 0ull;
            #pragma unroll
            for (int qi = 0; qi < 8; qi++) {
                u64 pq = __shfl_sync(FULL, s, qi, 32);
                acc = ffma2(pq, g4p[qi][tid], acc);
            }
            float lo, hi; upk2(acc, lo, hi);
            Ash[tid] = lo + hi;
        }
        __syncthreads();                               // BAR2

        // ---- stage 2: 4 shared A-rows, both units ----
        u64 a0 = pk2(ihg1.x, 0.f), a1 = pk2(ihg1.y, 0.f);
        u64 a2 = pk2(ihg1.z, 0.f), a3 = pk2(ihg1.w, 0.f);
        u64 b0 = pk2(ihg2.x, 0.f), b1 = pk2(ihg2.y, 0.f);
        u64 b2 = pk2(ihg2.z, 0.f), b3 = pk2(ihg2.w, 0.f);
        {
            const ulonglong2* R0 = (const ulonglong2*)(Ash + (0 * 4 + nr) * 16);
            const ulonglong2* R1 = (const ulonglong2*)(Ash + (1 * 4 + nr) * 16);
            const ulonglong2* R2 = (const ulonglong2*)(Ash + (2 * 4 + nr) * 16);
            const ulonglong2* R3 = (const ulonglong2*)(Ash + (3 * 4 + nr) * 16);
            #pragma unroll
            for (int i = 0; i < 4; i++) {
                u64 gA1 = Gp1[2 * i], gB1 = Gp1[2 * i + 1];
                u64 gA2 = Gp2[2 * i], gB2 = Gp2[2 * i + 1];
                ulonglong2 w;
                w = R0[i];
                a0 = ffma2(w.x, gA1, a0); a0 = ffma2(w.y, gB1, a0);
                b0 = ffma2(w.x, gA2, b0); b0 = ffma2(w.y, gB2, b0);
                w = R1[i];
                a1 = ffma2(w.x, gA1, a1); a1 = ffma2(w.y, gB1, a1);
                b1 = ffma2(w.x, gA2, b1); b1 = ffma2(w.y, gB2, b1);
                w = R2[i];
                a2 = ffma2(w.x, gA1, a2); a2 = ffma2(w.y, gB1, a2);
                b2 = ffma2(w.x, gA2, b2); b2 = ffma2(w.y, gB2, b2);
                w = R3[i];
                a3 = ffma2(w.x, gA1, a3); a3 = ffma2(w.y, gB1, a3);
                b3 = ffma2(w.x, gA2, b3); b3 = ffma2(w.y, gB2, b3);
            }
        }
        float xlo, xhi, gi1, gf1, gg1, go1, gi2, gf2, gg2, go2;
        upk2(a0, xlo, xhi); gi1 = xlo + xhi;
        upk2(a1, xlo, xhi); gf1 = xlo + xhi;
        upk2(a2, xlo, xhi); gg1 = xlo + xhi;
        upk2(a3, xlo, xhi); go1 = xlo + xhi;
        upk2(b0, xlo, xhi); gi2 = xlo + xhi;
        upk2(b1, xlo, xhi); gf2 = xlo + xhi;
        upk2(b2, xlo, xhi); gg2 = xlo + xhi;
        upk2(b3, xlo, xhi); go2 = xlo + xhi;

        // ---- LSTM cell (HW tanh) ----
        c1 = hsig(gf1) * c1 + hsig(gi1) * htanh(gg1);
        h1 = hsig(go1) * htanh(c1);
        c2 = hsig(gf2) * c2 + hsig(gi2) * htanh(gg2);
        h2 = hsig(go2) * htanh(c2);

        // duplicated h store (1 STS.128) + gmem output
        *(float4*)(hdup + 2 * j0) = make_float4(h1, h1, h2, h2);
        *(float2*)(outb + (size_t)t * DH + j0) = make_float2(h1, h2);
        ihg1 = ihg1n; ihg2 = ihg2n;
        cN = cN2;
        __syncthreads();                               // BAR3 (protect hdup)
    }

    // final (h, c) appended after output tensor
    float* hc = out + (size_t)BB * TT * DH;
    *(float2*)(hc + b * DH + j0) = make_float2(h1, h2);
    *(float2*)(hc + (size_t)BB * DH + b * DH + j0) = make_float2(c1, c2);
}

// ---------------- launcher -------------------------------------------------
extern "C" void kernel_launch(void* const* d_in, const int* in_sizes, int n_in,
                              void* d_out, int out_size)
{
    const float* x    = (const float*)d_in[0];
    const float* ih1  = (const float*)d_in[1];
    const float* ih2  = (const float*)d_in[2];
    const float* ih3  = (const float*)d_in[3];
    const float* ih4  = (const float*)d_in[4];
    const float* ih5  = (const float*)d_in[5];
    const float* ih6  = (const float*)d_in[6];
    const float* hh1  = (const float*)d_in[7];
    const float* hh2  = (const float*)d_in[8];
    const float* hh3  = (const float*)d_in[9];
    const float* hh4  = (const float*)d_in[10];
    const float* hh5  = (const float*)d_in[11];
    const float* hh6  = (const float*)d_in[12];
    const float* bih  = (const float*)d_in[13];
    const float* bhh  = (const float*)d_in[14];
    float* out = (float*)d_out;

    k_build<<<2, 1024>>>(ih1, ih2, ih3, ih5, ih6,
                         hh1, hh2, hh3, hh5, hh6, bih, bhh);
    k_fused<<<BB + NPROD, 512>>>(x, ih4, hh4, out);
}

// round 11
// speedup vs baseline: 3.0994x; 3.0994x over previous
#include <cuda_runtime.h>
#include <cstdint>

#define BB   64
#define TT   512
#define DH   1024

// ---------------- device scratch (static, allocation-free) ----------------
__device__ float g_Gin_ih[1024 * 16];    // [j][d]
__device__ float g_Gin_hh[1024 * 16];    // [j][d]
__device__ float g_G56t_ih[256 * 16];    // [mp][e]  (transposed)
__device__ float g_G56t_hh[256 * 16];    // [mp][e]
__device__ float g_bias4[4096];          // [j][gate]
__device__ float g_ihg[(size_t)BB * TT * 4096]; // [b][t][j][gate]

typedef unsigned long long u64;

// ---------------- packed f32x2 helpers ------------------------------------
__device__ __forceinline__ u64 pk2(float lo, float hi) {
    u64 r; asm("mov.b64 %0, {%1,%2};" : "=l"(r) : "f"(lo), "f"(hi)); return r;
}
__device__ __forceinline__ void upk2(u64 v, float& lo, float& hi) {
    asm("mov.b64 {%0,%1}, %2;" : "=f"(lo), "=f"(hi) : "l"(v));
}
__device__ __forceinline__ u64 ffma2(u64 a, u64 b, u64 c) {
    u64 d; asm("fma.rn.f32x2 %0, %1, %2, %3;" : "=l"(d) : "l"(a), "l"(b), "l"(c));
    return d;
}
__device__ __forceinline__ u64 fadd2(u64 a, u64 b) {
    u64 d; asm("add.rn.f32x2 %0, %1, %2;" : "=l"(d) : "l"(a), "l"(b));
    return d;
}

// ---------------- activations ---------------------------------------------
__device__ __forceinline__ float htanh(float x) {
    float y; asm("tanh.approx.f32 %0, %1;" : "=f"(y) : "f"(x)); return y;
}
__device__ __forceinline__ float hsig(float x) {
    return fmaf(0.5f, htanh(0.5f * x), 0.5f);
}

// ---------------- kernel 0: build contraction tables (2 CTAs, 1/path) -----
__global__ void k_build(const float* g1i, const float* g2i, const float* g3i,
                        const float* g5i, const float* g6i,
                        const float* g1h, const float* g2h, const float* g3h,
                        const float* g5h, const float* g6h,
                        const float* bih, const float* bhh)
{
    __shared__ float G12[1024]; // [i][j][c]
    int tid  = threadIdx.x;     // 1024 threads
    int path = blockIdx.x;      // 0 = ih, 1 = hh

    const float* g1 = path ? g1h : g1i;
    const float* g2 = path ? g2h : g2i;
    const float* g3 = path ? g3h : g3i;
    const float* g5 = path ? g5h : g5i;
    const float* g6 = path ? g6h : g6i;
    float* Gin  = path ? g_Gin_hh  : g_Gin_ih;
    float* G56t = path ? g_G56t_hh : g_G56t_ih;

    { // G12[i][j][c] = sum_a g1[i,a] g2[a,j,c]
        int i = tid >> 7, j = (tid >> 4) & 7, c = tid & 15;
        float s = 0.f;
        #pragma unroll
        for (int a = 0; a < 16; a++)
            s = fmaf(g1[i * 16 + a], g2[a * 128 + j * 16 + c], s);
        G12[tid] = s;
    }
    __syncthreads();
    // Gin[(i,j,k)][d] = sum_c G12[i,j,c] g3[c,k,d]
    for (int o = tid; o < 16384; o += 1024) {
        int row = o >> 4, d = o & 15;
        int i = row >> 7, j = (row >> 4) & 7, k = row & 15;
        float s = 0.f;
        #pragma unroll
        for (int c = 0; c < 16; c++)
            s = fmaf(G12[i * 128 + j * 16 + c], g3[c * 256 + k * 16 + d], s);
        Gin[row * 16 + d] = s;
    }
    // G56t[mp][e] = sum_f g5[e,m,f] g6[f,p]
    for (int o = tid; o < 4096; o += 1024) {
        int e = o >> 8, m = (o >> 4) & 15, p = o & 15;
        float s = 0.f;
        #pragma unroll
        for (int f = 0; f < 16; f++)
            s = fmaf(g5[e * 256 + m * 16 + f], g6[f * 16 + p], s);
        G56t[(m * 16 + p) * 16 + e] = s;
    }
    if (path == 0) { // bias reindexed to [j][gate]
        int j = tid;
        float4 v;
        v.x = bih[j]        + bhh[j];
        v.y = bih[1024 + j] + bhh[1024 + j];
        v.z = bih[2048 + j] + bhh[2048 + j];
        v.w = bih[3072 + j] + bhh[3072 + j];
        ((float4*)g_bias4)[j] = v;
    }
}

// ---------------- kernel 1: precompute ih gates for all (b,t) -------------
__global__ void __launch_bounds__(256) k_pre(const float* __restrict__ x,
                                             const float* __restrict__ g4i)
{
    __shared__ float xs[1024];
    __shared__ float pp[16][17];
    __shared__ float ihp[16];
    __shared__ __align__(16) float A[256]; // [n][e]

    int rb  = blockIdx.x;
    int tid = threadIdx.x;

    ((float4*)xs)[tid] = ((const float4*)(x + (size_t)rb * 1024))[tid];
    __syncthreads();

    { // ihp[d] = sum_j xs[j] * Gin_ih[j][d]
        int d = tid & 15, ch = tid >> 4;
        const float* gp = g_Gin_ih + (ch * 64) * 16 + d;
        const float* xp = xs + ch * 64;
        float s = 0.f;
        #pragma unroll
        for (int u = 0; u < 64; u++) s = fmaf(xp[u], gp[u * 16], s);
        pp[ch][d] = s;
    }
    __syncthreads();
    if (tid < 16) {
        float s = 0.f;
        #pragma unroll
        for (int c2 = 0; c2 < 16; c2++) s += pp[c2][tid];
        ihp[tid] = s;
    }
    __syncthreads();
    { // A[n][e] = sum_d ihp[d] * g4_ih[d][n][e]
        int n = tid >> 4, e = tid & 15;
        float s = 0.f;
        #pragma unroll
        for (int d = 0; d < 16; d++)
            s = fmaf(ihp[d], __ldg(g4i + d * 256 + n * 16 + e), s);
        A[tid] = s;
    }
    __syncthreads();

    // stage2 (packed over e-pairs): mp = tid
    u64 Gp[8];
    {
        const u64* gt = (const u64*)(g_G56t_ih + tid * 16);
        #pragma unroll
        for (int i = 0; i < 8; i++) Gp[i] = gt[i];
    }
    float* outp = g_ihg + (size_t)rb * 4096;
    #pragma unroll
    for (int k = 0; k < 4; k++) {
        int j = k * 256 + tid;
        float4 bv = ((const float4*)g_bias4)[j];
        u64 a0 = 0ull, a1 = 0ull, a2 = 0ull, a3 = 0ull;
        const ulonglong2* Ar0 = (const ulonglong2*)(A + (0 * 4 + k) * 16);
        const ulonglong2* Ar1 = (const ulonglong2*)(A + (1 * 4 + k) * 16);
        const ulonglong2* Ar2 = (const ulonglong2*)(A + (2 * 4 + k) * 16);
        const ulonglong2* Ar3 = (const ulonglong2*)(A + (3 * 4 + k) * 16);
        #pragma unroll
        for (int i = 0; i < 4; i++) {
            ulonglong2 w0 = Ar0[i], w1 = Ar1[i], w2 = Ar2[i], w3 = Ar3[i];
            a0 = ffma2(w0.x, Gp[2 * i], a0); a0 = ffma2(w0.y, Gp[2 * i + 1], a0);
            a1 = ffma2(w1.x, Gp[2 * i], a1); a1 = ffma2(w1.y, Gp[2 * i + 1], a1);
            a2 = ffma2(w2.x, Gp[2 * i], a2); a2 = ffma2(w2.y, Gp[2 * i + 1], a2);
            a3 = ffma2(w3.x, Gp[2 * i], a3); a3 = ffma2(w3.y, Gp[2 * i + 1], a3);
        }
        float l0, h0, l1, h1, l2, h2, l3, h3;
        upk2(a0, l0, h0); upk2(a1, l1, h1);
        upk2(a2, l2, h2); upk2(a3, l3, h3);
        float4 v;
        v.x = l0 + h0 + bv.x; v.y = l1 + h1 + bv.y;
        v.z = l2 + h2 + bv.z; v.w = l3 + h3 + bv.w;
        ((float4*)outp)[j] = v;
    }
}

// ---------------- kernel 2: recurrence ------------------------------------
// 64 CTAs x 512 threads; thread owns ADJACENT units j0=2*tid, j0+1.
// h stored DUPLICATED in smem (hdup[2j]={h,h}): phase1 loads ready-packed
// f32x2 operands via LDS.128 (no pk2 movs), dual accumulator chains.
__global__ void __launch_bounds__(512, 1) k_rec(const float* __restrict__ g4h,
                                                float* __restrict__ out)
{
    __shared__ __align__(16) float hdup[2048];   // h duplicated {h,h}
    __shared__ u64 g4p[8][256];                  // paired g4: (d=2q, 2q+1)
    __shared__ __align__(16) float Ash[256];     // [n][e]
    __shared__ u64 ppu[16][8];                   // [warp][d-pair]

    int tid = threadIdx.x;
    int b   = blockIdx.x;
    const unsigned FULL = 0xffffffffu;

    // build paired g4 in smem; zero hdup
    for (int i = tid; i < 2048; i += 512) {
        int qq = i >> 8, col = i & 255;
        g4p[qq][col] = pk2(g4h[(2 * qq) * 256 + col], g4h[(2 * qq + 1) * 256 + col]);
        hdup[i] = 0.f;
    }

    // ---- phase-1 constants: thread = (j-chunk ch, d-pair q) ----
    int q  = tid & 7;                    // d-pair
    int ch = tid >> 3;                   // chunk 0..63 (8 j's), + chunk ch+64
    u64 Grp1[8], Grp2[8];
    {
        const float* gb1 = g_Gin_hh + (size_t)(ch * 8) * 16 + 2 * q;
        const float* gb2 = gb1 + 512 * 16;
        #pragma unroll
        for (int u = 0; u < 8; u++) {
            Grp1[u] = *(const u64*)(gb1 + u * 16);
            Grp2[u] = *(const u64*)(gb2 + u * 16);
        }
    }
    // ---- stage-2 constants: adjacent unit pair ----
    int j0  = 2 * tid;                   // units j0, j0+1
    int mp1 = j0 & 255, mp2 = mp1 + 1;
    int nr  = tid >> 7;                  // shared n-index: rows g*4 + nr
    u64 Gp1[8], Gp2[8];
    {
        const u64* gt1 = (const u64*)(g_G56t_hh + mp1 * 16);
        const u64* gt2 = (const u64*)(g_G56t_hh + mp2 * 16);
        #pragma unroll
        for (int i = 0; i < 8; i++) { Gp1[i] = gt1[i]; Gp2[i] = gt2[i]; }
    }
    int warp = tid >> 5, lane = tid & 31;

    float h1 = 0.f, c1 = 0.f, h2 = 0.f, c2 = 0.f;
    const float* ihp = g_ihg + (size_t)b * TT * 4096 + (size_t)j0 * 4;
    float* outb = out + (size_t)b * TT * DH;

    float4 ihg1 = ((const float4*)ihp)[0];       // t=0, unit j0
    float4 ihg2 = ((const float4*)ihp)[1];       //      unit j0+1

    __syncthreads();

    for (int t = 0; t < TT; t++) {
        // ---- phase 1: duplicated-h LDS.128 loads, dual ffma2 chains ----
        const ulonglong2* hp1 = (const ulonglong2*)(hdup + ch * 16);
        const ulonglong2* hp2 = (const ulonglong2*)(hdup + 1024 + ch * 16);
        u64 pa, pb;
        {
            ulonglong2 wA = hp1[0], wB = hp2[0];
            pa = ffma2(wA.x, Grp1[0], 0ull); pa = ffma2(wA.y, Grp1[1], pa);
            pb = ffma2(wB.x, Grp2[0], 0ull); pb = ffma2(wB.y, Grp2[1], pb);
            wA = hp1[1]; wB = hp2[1];
            pa = ffma2(wA.x, Grp1[2], pa);   pa = ffma2(wA.y, Grp1[3], pa);
            pb = ffma2(wB.x, Grp2[2], pb);   pb = ffma2(wB.y, Grp2[3], pb);
            wA = hp1[2]; wB = hp2[2];
            pa = ffma2(wA.x, Grp1[4], pa);   pa = ffma2(wA.y, Grp1[5], pa);
            pb = ffma2(wB.x, Grp2[4], pb);   pb = ffma2(wB.y, Grp2[5], pb);
            wA = hp1[3]; wB = hp2[3];
            pa = ffma2(wA.x, Grp1[6], pa);   pa = ffma2(wA.y, Grp1[7], pa);
            pb = ffma2(wB.x, Grp2[6], pb);   pb = ffma2(wB.y, Grp2[7], pb);
        }
        u64 part = fadd2(pa, pb);
        part = fadd2(part, __shfl_xor_sync(FULL, part, 8));
        part = fadd2(part, __shfl_xor_sync(FULL, part, 16));
        if (lane < 8) ppu[warp][lane] = part;

        // prefetch next step's ih gates (clamped, register-carried)
        int tn = (t + 1 < TT) ? (t + 1) : t;
        const float4* np = (const float4*)(ihp + (size_t)tn * 4096);
        float4 ihg1n = np[0];
        float4 ihg2n = np[1];
        __syncthreads();                               // BAR1

        // ---- fused reduce + stage 1 (warps 0-7; col = tid) ----
        if (tid < 256) {
            int w0 = lane >> 3, qq = lane & 7;
            u64 s = fadd2(fadd2(ppu[w0][qq], ppu[w0 + 4][qq]),
                          fadd2(ppu[w0 + 8][qq], ppu[w0 + 12][qq]));
            s = fadd2(s, __shfl_xor_sync(FULL, s, 8));
            s = fadd2(s, __shfl_xor_sync(FULL, s, 16));
            u64 acc = 0ull;
            #pragma unroll
            for (int qi = 0; qi < 8; qi++) {
                u64 pq = __shfl_sync(FULL, s, qi, 32);
                acc = ffma2(pq, g4p[qi][tid], acc);
            }
            float lo, hi; upk2(acc, lo, hi);
            Ash[tid] = lo + hi;
        }
        __syncthreads();                               // BAR2

        // ---- stage 2: 4 shared A-rows, both units ----
        u64 a0 = pk2(ihg1.x, 0.f), a1 = pk2(ihg1.y, 0.f);
        u64 a2 = pk2(ihg1.z, 0.f), a3 = pk2(ihg1.w, 0.f);
        u64 b0 = pk2(ihg2.x, 0.f), b1 = pk2(ihg2.y, 0.f);
        u64 b2 = pk2(ihg2.z, 0.f), b3 = pk2(ihg2.w, 0.f);
        {
            const ulonglong2* R0 = (const ulonglong2*)(Ash + (0 * 4 + nr) * 16);
            const ulonglong2* R1 = (const ulonglong2*)(Ash + (1 * 4 + nr) * 16);
            const ulonglong2* R2 = (const ulonglong2*)(Ash + (2 * 4 + nr) * 16);
            const ulonglong2* R3 = (const ulonglong2*)(Ash + (3 * 4 + nr) * 16);
            #pragma unroll
            for (int i = 0; i < 4; i++) {
                u64 gA1 = Gp1[2 * i], gB1 = Gp1[2 * i + 1];
                u64 gA2 = Gp2[2 * i], gB2 = Gp2[2 * i + 1];
                ulonglong2 w;
                w = R0[i];
                a0 = ffma2(w.x, gA1, a0); a0 = ffma2(w.y, gB1, a0);
                b0 = ffma2(w.x, gA2, b0); b0 = ffma2(w.y, gB2, b0);
                w = R1[i];
                a1 = ffma2(w.x, gA1, a1); a1 = ffma2(w.y, gB1, a1);
                b1 = ffma2(w.x, gA2, b1); b1 = ffma2(w.y, gB2, b1);
                w = R2[i];
                a2 = ffma2(w.x, gA1, a2); a2 = ffma2(w.y, gB1, a2);
                b2 = ffma2(w.x, gA2, b2); b2 = ffma2(w.y, gB2, b2);
                w = R3[i];
                a3 = ffma2(w.x, gA1, a3); a3 = ffma2(w.y, gB1, a3);
                b3 = ffma2(w.x, gA2, b3); b3 = ffma2(w.y, gB2, b3);
            }
        }
        float xlo, xhi, gi1, gf1, gg1, go1, gi2, gf2, gg2, go2;
        upk2(a0, xlo, xhi); gi1 = xlo + xhi;
        upk2(a1, xlo, xhi); gf1 = xlo + xhi;
        upk2(a2, xlo, xhi); gg1 = xlo + xhi;
        upk2(a3, xlo, xhi); go1 = xlo + xhi;
        upk2(b0, xlo, xhi); gi2 = xlo + xhi;
        upk2(b1, xlo, xhi); gf2 = xlo + xhi;
        upk2(b2, xlo, xhi); gg2 = xlo + xhi;
        upk2(b3, xlo, xhi); go2 = xlo + xhi;

        // ---- LSTM cell (HW tanh) ----
        c1 = hsig(gf1) * c1 + hsig(gi1) * htanh(gg1);
        h1 = hsig(go1) * htanh(c1);
        c2 = hsig(gf2) * c2 + hsig(gi2) * htanh(gg2);
        h2 = hsig(go2) * htanh(c2);

        // duplicated h store (1 STS.128) + gmem output
        *(float4*)(hdup + 2 * j0) = make_float4(h1, h1, h2, h2);
        *(float2*)(outb + (size_t)t * DH + j0) = make_float2(h1, h2);
        ihg1 = ihg1n; ihg2 = ihg2n;
        __syncthreads();                               // BAR3 (protect hdup)
    }

    // final (h, c) appended after output tensor
    float* hc = out + (size_t)BB * TT * DH;
    *(float2*)(hc + b * DH + j0) = make_float2(h1, h2);
    *(float2*)(hc + (size_t)BB * DH + b * DH + j0) = make_float2(c1, c2);
}

// ---------------- launcher -------------------------------------------------
extern "C" void kernel_launch(void* const* d_in, const int* in_sizes, int n_in,
                              void* d_out, int out_size)
{
    const float* x    = (const float*)d_in[0];
    const float* ih1  = (const float*)d_in[1];
    const float* ih2  = (const float*)d_in[2];
    const float* ih3  = (const float*)d_in[3];
    const float* ih4  = (const float*)d_in[4];
    const float* ih5  = (const float*)d_in[5];
    const float* ih6  = (const float*)d_in[6];
    const float* hh1  = (const float*)d_in[7];
    const float* hh2  = (const float*)d_in[8];
    const float* hh3  = (const float*)d_in[9];
    const float* hh4  = (const float*)d_in[10];
    const float* hh5  = (const float*)d_in[11];
    const float* hh6  = (const float*)d_in[12];
    const float* bih  = (const float*)d_in[13];
    const float* bhh  = (const float*)d_in[14];
    float* out = (float*)d_out;

    k_build<<<2, 1024>>>(ih1, ih2, ih3, ih5, ih6,
                         hh1, hh2, hh3, hh5, hh6, bih, bhh);
    k_pre<<<BB * TT, 256>>>(x, ih4);
    k_rec<<<BB, 512>>>(hh4, out);
}

// round 12
// speedup vs baseline: 3.5860x; 1.1570x over previous
#include <cuda_runtime.h>
#include <cuda_fp16.h>
#include <cstdint>

#define BB   64
#define TT   512
#define DH   1024

// ---------------- device scratch (static, allocation-free) ----------------
__device__ float g_Gin_ih[1024 * 16];    // [j][d]
__device__ float g_Gin_hh[1024 * 16];    // [j][d]
__device__ float g_G56t_ih[256 * 16];    // [mp][e]  (transposed)
__device__ float g_G56t_hh[256 * 16];    // [mp][e]
__device__ float g_bias4[4096];          // [j][gate]
__device__ __half g_ihg[(size_t)BB * TT * 4096]; // [b][t][j][gate], fp16

typedef unsigned long long u64;

// ---------------- packed f32x2 helpers ------------------------------------
__device__ __forceinline__ u64 pk2(float lo, float hi) {
    u64 r; asm("mov.b64 %0, {%1,%2};" : "=l"(r) : "f"(lo), "f"(hi)); return r;
}
__device__ __forceinline__ void upk2(u64 v, float& lo, float& hi) {
    asm("mov.b64 {%0,%1}, %2;" : "=f"(lo), "=f"(hi) : "l"(v));
}
__device__ __forceinline__ u64 ffma2(u64 a, u64 b, u64 c) {
    u64 d; asm("fma.rn.f32x2 %0, %1, %2, %3;" : "=l"(d) : "l"(a), "l"(b), "l"(c));
    return d;
}
__device__ __forceinline__ u64 fadd2(u64 a, u64 b) {
    u64 d; asm("add.rn.f32x2 %0, %1, %2;" : "=l"(d) : "l"(a), "l"(b));
    return d;
}

// ---------------- activations ---------------------------------------------
__device__ __forceinline__ float htanh(float x) {
    float y; asm("tanh.approx.f32 %0, %1;" : "=f"(y) : "f"(x)); return y;
}
__device__ __forceinline__ float hsig(float x) {
    return fmaf(0.5f, htanh(0.5f * x), 0.5f);
}

// ---------------- kernel 0: build contraction tables (2 CTAs, 1/path) -----
__global__ void k_build(const float* g1i, const float* g2i, const float* g3i,
                        const float* g5i, const float* g6i,
                        const float* g1h, const float* g2h, const float* g3h,
                        const float* g5h, const float* g6h,
                        const float* bih, const float* bhh)
{
    __shared__ float G12[1024]; // [i][j][c]
    int tid  = threadIdx.x;     // 1024 threads
    int path = blockIdx.x;      // 0 = ih, 1 = hh

    const float* g1 = path ? g1h : g1i;
    const float* g2 = path ? g2h : g2i;
    const float* g3 = path ? g3h : g3i;
    const float* g5 = path ? g5h : g5i;
    const float* g6 = path ? g6h : g6i;
    float* Gin  = path ? g_Gin_hh  : g_Gin_ih;
    float* G56t = path ? g_G56t_hh : g_G56t_ih;

    { // G12[i][j][c] = sum_a g1[i,a] g2[a,j,c]
        int i = tid >> 7, j = (tid >> 4) & 7, c = tid & 15;
        float s = 0.f;
        #pragma unroll
        for (int a = 0; a < 16; a++)
            s = fmaf(g1[i * 16 + a], g2[a * 128 + j * 16 + c], s);
        G12[tid] = s;
    }
    __syncthreads();
    // Gin[(i,j,k)][d] = sum_c G12[i,j,c] g3[c,k,d]
    for (int o = tid; o < 16384; o += 1024) {
        int row = o >> 4, d = o & 15;
        int i = row >> 7, j = (row >> 4) & 7, k = row & 15;
        float s = 0.f;
        #pragma unroll
        for (int c = 0; c < 16; c++)
            s = fmaf(G12[i * 128 + j * 16 + c], g3[c * 256 + k * 16 + d], s);
        Gin[row * 16 + d] = s;
    }
    // G56t[mp][e] = sum_f g5[e,m,f] g6[f,p]
    for (int o = tid; o < 4096; o += 1024) {
        int e = o >> 8, m = (o >> 4) & 15, p = o & 15;
        float s = 0.f;
        #pragma unroll
        for (int f = 0; f < 16; f++)
            s = fmaf(g5[e * 256 + m * 16 + f], g6[f * 16 + p], s);
        G56t[(m * 16 + p) * 16 + e] = s;
    }
    if (path == 0) { // bias reindexed to [j][gate]
        int j = tid;
        float4 v;
        v.x = bih[j]        + bhh[j];
        v.y = bih[1024 + j] + bhh[1024 + j];
        v.z = bih[2048 + j] + bhh[2048 + j];
        v.w = bih[3072 + j] + bhh[3072 + j];
        ((float4*)g_bias4)[j] = v;
    }
}

// ---------------- kernel 1: precompute ih gates for all (b,t) -------------
// output in fp16 (halves the 512MB g_ihg write stream -> DRAM-bound win)
__global__ void __launch_bounds__(256) k_pre(const float* __restrict__ x,
                                             const float* __restrict__ g4i)
{
    __shared__ float xs[1024];
    __shared__ float pp[16][17];
    __shared__ float ihp[16];
    __shared__ __align__(16) float A[256]; // [n][e]

    int rb  = blockIdx.x;
    int tid = threadIdx.x;

    ((float4*)xs)[tid] = ((const float4*)(x + (size_t)rb * 1024))[tid];
    __syncthreads();

    { // ihp[d] = sum_j xs[j] * Gin_ih[j][d]
        int d = tid & 15, ch = tid >> 4;
        const float* gp = g_Gin_ih + (ch * 64) * 16 + d;
        const float* xp = xs + ch * 64;
        float s = 0.f;
        #pragma unroll
        for (int u = 0; u < 64; u++) s = fmaf(xp[u], gp[u * 16], s);
        pp[ch][d] = s;
    }
    __syncthreads();
    if (tid < 16) {
        float s = 0.f;
        #pragma unroll
        for (int c2 = 0; c2 < 16; c2++) s += pp[c2][tid];
        ihp[tid] = s;
    }
    __syncthreads();
    { // A[n][e] = sum_d ihp[d] * g4_ih[d][n][e]
        int n = tid >> 4, e = tid & 15;
        float s = 0.f;
        #pragma unroll
        for (int d = 0; d < 16; d++)
            s = fmaf(ihp[d], __ldg(g4i + d * 256 + n * 16 + e), s);
        A[tid] = s;
    }
    __syncthreads();

    // stage2 (packed over e-pairs): mp = tid
    u64 Gp[8];
    {
        const u64* gt = (const u64*)(g_G56t_ih + tid * 16);
        #pragma unroll
        for (int i = 0; i < 8; i++) Gp[i] = gt[i];
    }
    __half* outp = g_ihg + (size_t)rb * 4096;
    #pragma unroll
    for (int k = 0; k < 4; k++) {
        int j = k * 256 + tid;
        float4 bv = ((const float4*)g_bias4)[j];
        u64 a0 = 0ull, a1 = 0ull, a2 = 0ull, a3 = 0ull;
        const ulonglong2* Ar0 = (const ulonglong2*)(A + (0 * 4 + k) * 16);
        const ulonglong2* Ar1 = (const ulonglong2*)(A + (1 * 4 + k) * 16);
        const ulonglong2* Ar2 = (const ulonglong2*)(A + (2 * 4 + k) * 16);
        const ulonglong2* Ar3 = (const ulonglong2*)(A + (3 * 4 + k) * 16);
        #pragma unroll
        for (int i = 0; i < 4; i++) {
            ulonglong2 w0 = Ar0[i], w1 = Ar1[i], w2 = Ar2[i], w3 = Ar3[i];
            a0 = ffma2(w0.x, Gp[2 * i], a0); a0 = ffma2(w0.y, Gp[2 * i + 1], a0);
            a1 = ffma2(w1.x, Gp[2 * i], a1); a1 = ffma2(w1.y, Gp[2 * i + 1], a1);
            a2 = ffma2(w2.x, Gp[2 * i], a2); a2 = ffma2(w2.y, Gp[2 * i + 1], a2);
            a3 = ffma2(w3.x, Gp[2 * i], a3); a3 = ffma2(w3.y, Gp[2 * i + 1], a3);
        }
        float l0, h0, l1, h1, l2, h2, l3, h3;
        upk2(a0, l0, h0); upk2(a1, l1, h1);
        upk2(a2, l2, h2); upk2(a3, l3, h3);
        __half2 v01 = __floats2half2_rn(l0 + h0 + bv.x, l1 + h1 + bv.y);
        __half2 v23 = __floats2half2_rn(l2 + h2 + bv.z, l3 + h3 + bv.w);
        uint2 st;
        st.x = *(const unsigned int*)&v01;
        st.y = *(const unsigned int*)&v23;
        ((uint2*)outp)[j] = st;   // 4 halves per j
    }
}

// ---------------- kernel 2: recurrence (R8 structure + dual chains) -------
// 64 CTAs x 512 threads; thread owns ADJACENT units j0=2*tid, j0+1 (same
// A-rows -> stage2 LDS halved; STG.64 h-store). h in smem (unduplicated):
// phase1 gathers via 4 LDS.128 + pk2 movs (movs are FMA-pipe, MIO is the
// bottleneck). fp16 ihg: 1 LDG.128 covers both units' gates.
__global__ void __launch_bounds__(512, 1) k_rec(const float* __restrict__ g4h,
                                                float* __restrict__ out)
{
    __shared__ __align__(16) float hsm[1024];    // h state in smem
    __shared__ u64 g4p[8][256];                  // paired g4: (d=2q, 2q+1)
    __shared__ __align__(16) float Ash[256];     // [n][e]
    __shared__ u64 ppu[16][8];                   // [warp][d-pair]

    int tid = threadIdx.x;
    int b   = blockIdx.x;
    const unsigned FULL = 0xffffffffu;

    // build paired g4 in smem; zero hsm
    for (int i = tid; i < 2048; i += 512) {
        int qq = i >> 8, col = i & 255;
        g4p[qq][col] = pk2(g4h[(2 * qq) * 256 + col], g4h[(2 * qq + 1) * 256 + col]);
    }
    hsm[tid] = 0.f;
    hsm[tid + 512] = 0.f;

    // ---- phase-1 constants: thread = (j-chunk ch, d-pair q) ----
    int q  = tid & 7;                    // d-pair
    int ch = tid >> 3;                   // chunk 0..63 (8 j's), + chunk ch+64
    u64 Grp1[8], Grp2[8];
    {
        const float* gb1 = g_Gin_hh + (size_t)(ch * 8) * 16 + 2 * q;
        const float* gb2 = gb1 + 512 * 16;
        #pragma unroll
        for (int u = 0; u < 8; u++) {
            Grp1[u] = *(const u64*)(gb1 + u * 16);
            Grp2[u] = *(const u64*)(gb2 + u * 16);
        }
    }
    // ---- stage-2 constants: adjacent unit pair ----
    int j0  = 2 * tid;                   // units j0, j0+1
    int mp1 = j0 & 255, mp2 = mp1 + 1;
    int nr  = tid >> 7;                  // shared n-index: rows g*4 + nr
    u64 Gp1[8], Gp2[8];
    {
        const u64* gt1 = (const u64*)(g_G56t_hh + mp1 * 16);
        const u64* gt2 = (const u64*)(g_G56t_hh + mp2 * 16);
        #pragma unroll
        for (int i = 0; i < 8; i++) { Gp1[i] = gt1[i]; Gp2[i] = gt2[i]; }
    }
    int warp = tid >> 5, lane = tid & 31;

    float h1 = 0.f, c1 = 0.f, h2 = 0.f, c2 = 0.f;
    const __half* ihp = g_ihg + (size_t)b * TT * 4096 + (size_t)j0 * 4;
    float* outb = out + (size_t)b * TT * DH;

    uint4 ihgr = *(const uint4*)ihp;             // t=0: 8 halves (both units)

    __syncthreads();

    for (int t = 0; t < TT; t++) {
        // ---- phase 1: LDS.128 h loads, pk2 packing, DUAL ffma2 chains ----
        const float4* hp1 = (const float4*)(hsm + ch * 8);
        const float4* hp2 = (const float4*)(hsm + 512 + ch * 8);
        float4 ha = hp1[0], hb = hp1[1];
        float4 hc_ = hp2[0], hd = hp2[1];
        u64 pa, pb;
        pa = ffma2(pk2(ha.x, ha.x), Grp1[0], 0ull);
        pb = ffma2(pk2(hc_.x, hc_.x), Grp2[0], 0ull);
        pa = ffma2(pk2(ha.y, ha.y), Grp1[1], pa);
        pb = ffma2(pk2(hc_.y, hc_.y), Grp2[1], pb);
        pa = ffma2(pk2(ha.z, ha.z), Grp1[2], pa);
        pb = ffma2(pk2(hc_.z, hc_.z), Grp2[2], pb);
        pa = ffma2(pk2(ha.w, ha.w), Grp1[3], pa);
        pb = ffma2(pk2(hc_.w, hc_.w), Grp2[3], pb);
        pa = ffma2(pk2(hb.x, hb.x), Grp1[4], pa);
        pb = ffma2(pk2(hd.x, hd.x), Grp2[4], pb);
        pa = ffma2(pk2(hb.y, hb.y), Grp1[5], pa);
        pb = ffma2(pk2(hd.y, hd.y), Grp2[5], pb);
        pa = ffma2(pk2(hb.z, hb.z), Grp1[6], pa);
        pb = ffma2(pk2(hd.z, hd.z), Grp2[6], pb);
        pa = ffma2(pk2(hb.w, hb.w), Grp1[7], pa);
        pb = ffma2(pk2(hd.w, hd.w), Grp2[7], pb);
        u64 part = fadd2(pa, pb);
        part = fadd2(part, __shfl_xor_sync(FULL, part, 8));
        part = fadd2(part, __shfl_xor_sync(FULL, part, 16));
        if (lane < 8) ppu[warp][lane] = part;

        // prefetch next step's ih gates (clamped, register-carried, fp16)
        int tn = (t + 1 < TT) ? (t + 1) : t;
        uint4 ihgn = *(const uint4*)(ihp + (size_t)tn * 4096);
        __syncthreads();                               // BAR1

        // ---- fused reduce + stage 1 (warps 0-7; col = tid) ----
        if (tid < 256) {
            int w0 = lane >> 3, qq = lane & 7;
            u64 s = fadd2(fadd2(ppu[w0][qq], ppu[w0 + 4][qq]),
                          fadd2(ppu[w0 + 8][qq], ppu[w0 + 12][qq]));
            s = fadd2(s, __shfl_xor_sync(FULL, s, 8));
            s = fadd2(s, __shfl_xor_sync(FULL, s, 16));
            u64 acc = 0ull;
            #pragma unroll
            for (int qi = 0; qi < 8; qi++) {
                u64 pq = __shfl_sync(FULL, s, qi, 32);
                acc = ffma2(pq, g4p[qi][tid], acc);
            }
            float lo, hi; upk2(acc, lo, hi);
            Ash[tid] = lo + hi;
        }
        __syncthreads();                               // BAR2

        // ---- decode fp16 gates for this step ----
        float2 f01 = __half22float2(*(const __half2*)&ihgr.x);  // j0: i,f
        float2 f23 = __half22float2(*(const __half2*)&ihgr.y);  // j0: g,o
        float2 f45 = __half22float2(*(const __half2*)&ihgr.z);  // j0+1: i,f
        float2 f67 = __half22float2(*(const __half2*)&ihgr.w);  // j0+1: g,o

        // ---- stage 2: 4 shared A-rows, both units ----
        u64 a0 = pk2(f01.x, 0.f), a1 = pk2(f01.y, 0.f);
        u64 a2 = pk2(f23.x, 0.f), a3 = pk2(f23.y, 0.f);
        u64 b0 = pk2(f45.x, 0.f), b1 = pk2(f45.y, 0.f);
        u64 b2 = pk2(f67.x, 0.f), b3 = pk2(f67.y, 0.f);
        {
            const ulonglong2* R0 = (const ulonglong2*)(Ash + (0 * 4 + nr) * 16);
            const ulonglong2* R1 = (const ulonglong2*)(Ash + (1 * 4 + nr) * 16);
            const ulonglong2* R2 = (const ulonglong2*)(Ash + (2 * 4 + nr) * 16);
            const ulonglong2* R3 = (const ulonglong2*)(Ash + (3 * 4 + nr) * 16);
            #pragma unroll
            for (int i = 0; i < 4; i++) {
                u64 gA1 = Gp1[2 * i], gB1 = Gp1[2 * i + 1];
                u64 gA2 = Gp2[2 * i], gB2 = Gp2[2 * i + 1];
                ulonglong2 w;
                w = R0[i];
                a0 = ffma2(w.x, gA1, a0); a0 = ffma2(w.y, gB1, a0);
                b0 = ffma2(w.x, gA2, b0); b0 = ffma2(w.y, gB2, b0);
                w = R1[i];
                a1 = ffma2(w.x, gA1, a1); a1 = ffma2(w.y, gB1, a1);
                b1 = ffma2(w.x, gA2, b1); b1 = ffma2(w.y, gB2, b1);
                w = R2[i];
                a2 = ffma2(w.x, gA1, a2); a2 = ffma2(w.y, gB1, a2);
                b2 = ffma2(w.x, gA2, b2); b2 = ffma2(w.y, gB2, b2);
                w = R3[i];
                a3 = ffma2(w.x, gA1, a3); a3 = ffma2(w.y, gB1, a3);
                b3 = ffma2(w.x, gA2, b3); b3 = ffma2(w.y, gB2, b3);
            }
        }
        float xlo, xhi, gi1, gf1, gg1, go1, gi2, gf2, gg2, go2;
        upk2(a0, xlo, xhi); gi1 = xlo + xhi;
        upk2(a1, xlo, xhi); gf1 = xlo + xhi;
        upk2(a2, xlo, xhi); gg1 = xlo + xhi;
        upk2(a3, xlo, xhi); go1 = xlo + xhi;
        upk2(b0, xlo, xhi); gi2 = xlo + xhi;
        upk2(b1, xlo, xhi); gf2 = xlo + xhi;
        upk2(b2, xlo, xhi); gg2 = xlo + xhi;
        upk2(b3, xlo, xhi); go2 = xlo + xhi;

        // ---- LSTM cell (HW tanh) ----
        c1 = hsig(gf1) * c1 + hsig(gi1) * htanh(gg1);
        h1 = hsig(go1) * htanh(c1);
        c2 = hsig(gf2) * c2 + hsig(gi2) * htanh(gg2);
        h2 = hsig(go2) * htanh(c2);

        // h store (STS.64) + gmem output (STG.64)
        *(float2*)(hsm + j0) = make_float2(h1, h2);
        *(float2*)(outb + (size_t)t * DH + j0) = make_float2(h1, h2);
        ihgr = ihgn;
        __syncthreads();                               // BAR3 (protect hsm)
    }

    // final (h, c) appended after output tensor
    float* hc = out + (size_t)BB * TT * DH;
    *(float2*)(hc + b * DH + j0) = make_float2(h1, h2);
    *(float2*)(hc + (size_t)BB * DH + b * DH + j0) = make_float2(c1, c2);
}

// ---------------- launcher -------------------------------------------------
extern "C" void kernel_launch(void* const* d_in, const int* in_sizes, int n_in,
                              void* d_out, int out_size)
{
    const float* x    = (const float*)d_in[0];
    const float* ih1  = (const float*)d_in[1];
    const float* ih2  = (const float*)d_in[2];
    const float* ih3  = (const float*)d_in[3];
    const float* ih4  = (const float*)d_in[4];
    const float* ih5  = (const float*)d_in[5];
    const float* ih6  = (const float*)d_in[6];
    const float* hh1  = (const float*)d_in[7];
    const float* hh2  = (const float*)d_in[8];
    const float* hh3  = (const float*)d_in[9];
    const float* hh4  = (const float*)d_in[10];
    const float* hh5  = (const float*)d_in[11];
    const float* hh6  = (const float*)d_in[12];
    const float* bih  = (const float*)d_in[13];
    const float* bhh  = (const float*)d_in[14];
    float* out = (float*)d_out;

    k_build<<<2, 1024>>>(ih1, ih2, ih3, ih5, ih6,
                         hh1, hh2, hh3, hh5, hh6, bih, bhh);
    k_pre<<<BB * TT, 256>>>(x, ih4);
    k_rec<<<BB, 512>>>(hh4, out);
}